// round 1
// baseline (speedup 1.0000x reference)
#include <cuda_runtime.h>

// ---------------------------------------------------------------------------
// KMeans assignment on GB300:
//   x: (8,4096,512) f32  -> B = 32768 points, D = 512
//   centroids: (2048,512) f32 -> K = 2048
// Outputs (tuple order): labels (B,) and assigned = centroids[labels] (B,512).
// argmin_k ||(x+eps) - c_k|| == argmin_k ( c_sq[k] - 2*(x+eps).c_k )
// ---------------------------------------------------------------------------

#define EPSF 1e-6f
#define DIMS 512
#define BM 128
#define BN 128
#define BK 32
#define MAX_B 32768
#define MAX_K 4096

__device__ int   g_labels[MAX_B];
__device__ float g_csq[MAX_K];

// ---- f32x2 packed helpers (Blackwell FFMA2, PTX-only) ----------------------
__device__ __forceinline__ unsigned long long pack2(float lo, float hi) {
    unsigned long long r;
    asm("mov.b64 %0, {%1, %2};" : "=l"(r) : "f"(lo), "f"(hi));
    return r;
}
__device__ __forceinline__ unsigned long long pack_bcast(float v) {
    unsigned long long r;
    asm("mov.b64 %0, {%1, %1};" : "=l"(r) : "f"(v));
    return r;
}
__device__ __forceinline__ unsigned long long ffma2(unsigned long long a,
                                                    unsigned long long b,
                                                    unsigned long long c) {
    unsigned long long d;
    asm("fma.rn.f32x2 %0, %1, %2, %3;" : "=l"(d) : "l"(a), "l"(b), "l"(c));
    return d;
}
__device__ __forceinline__ float2 unpack2(unsigned long long v) {
    float2 f;
    asm("mov.b64 {%0, %1}, %2;" : "=f"(f.x), "=f"(f.y) : "l"(v));
    return f;
}
// Order-preserving float->uint map (for packed argmin keys; lower idx wins ties)
__device__ __forceinline__ unsigned sortable_f32(float f) {
    unsigned u = __float_as_uint(f);
    return (u & 0x80000000u) ? ~u : (u | 0x80000000u);
}

// ---- kernel 1: centroid squared norms --------------------------------------
__global__ void csq_kernel(const float* __restrict__ cent, int K) {
    int k = blockIdx.x * blockDim.x + threadIdx.x;
    if (k >= K) return;
    const float4* row = reinterpret_cast<const float4*>(cent + (size_t)k * DIMS);
    float s = 0.f;
#pragma unroll 8
    for (int i = 0; i < DIMS / 4; ++i) {
        float4 v = row[i];
        s += v.x * v.x + v.y * v.y + v.z * v.z + v.w * v.w;
    }
    g_csq[k] = s;
}

// ---- kernel 2: fused distance-GEMM + argmin ---------------------------------
// Tile: BM=128 points x BN=128 centroids, K-chunks of 32.
// 256 threads, 8x8 microtile per thread; accumulators as f32x2 row-pairs.
__global__ __launch_bounds__(256, 2)
void assign_kernel(const float* __restrict__ x, const float* __restrict__ cent,
                   int K) {
    __shared__ float xs[BK][BM + 4];
    __shared__ float cs[BK][BN + 4];
    __shared__ unsigned long long best[BM];

    const int tid = threadIdx.x;
    const int m0 = blockIdx.x * BM;
    if (tid < BM) best[tid] = ~0ull;

    const int tx = tid & 15;
    const int ty = tid >> 4;
    const int rowbase = ty * 8;
    const int colbase = tx * 8;

    const int ntiles = K / BN;
    for (int nt = 0; nt < ntiles; ++nt) {
        const int n0 = nt * BN;

        unsigned long long acc[4][8];
#pragma unroll
        for (int i = 0; i < 4; ++i)
#pragma unroll
            for (int j = 0; j < 8; ++j) acc[i][j] = 0ull;

        for (int kt = 0; kt < DIMS / BK; ++kt) {
            const int k0 = kt * BK;
            __syncthreads();  // previous tile's consumers done (also orders best[] init)
            // Cooperative load: 128 rows x 8 float4-cols per matrix,
            // transposed into smem [k][row].
#pragma unroll
            for (int p = 0; p < 4; ++p) {
                int idx = p * 256 + tid;  // 0..1023
                int row = idx >> 3;
                int c4 = idx & 7;
                float4 v = *reinterpret_cast<const float4*>(
                    &x[(size_t)(m0 + row) * DIMS + k0 + c4 * 4]);
                v.x += EPSF; v.y += EPSF; v.z += EPSF; v.w += EPSF;
                xs[c4 * 4 + 0][row] = v.x;
                xs[c4 * 4 + 1][row] = v.y;
                xs[c4 * 4 + 2][row] = v.z;
                xs[c4 * 4 + 3][row] = v.w;
                float4 w = *reinterpret_cast<const float4*>(
                    &cent[(size_t)(n0 + row) * DIMS + k0 + c4 * 4]);
                cs[c4 * 4 + 0][row] = w.x;
                cs[c4 * 4 + 1][row] = w.y;
                cs[c4 * 4 + 2][row] = w.z;
                cs[c4 * 4 + 3][row] = w.w;
            }
            __syncthreads();

#pragma unroll
            for (int kk = 0; kk < BK; ++kk) {
                float4 a0 = *reinterpret_cast<const float4*>(&xs[kk][rowbase]);
                float4 a1 = *reinterpret_cast<const float4*>(&xs[kk][rowbase + 4]);
                float4 b0 = *reinterpret_cast<const float4*>(&cs[kk][colbase]);
                float4 b1 = *reinterpret_cast<const float4*>(&cs[kk][colbase + 4]);
                unsigned long long a2[4];
                a2[0] = pack2(a0.x, a0.y);
                a2[1] = pack2(a0.z, a0.w);
                a2[2] = pack2(a1.x, a1.y);
                a2[3] = pack2(a1.z, a1.w);
                unsigned long long bb[8];
                bb[0] = pack_bcast(b0.x);
                bb[1] = pack_bcast(b0.y);
                bb[2] = pack_bcast(b0.z);
                bb[3] = pack_bcast(b0.w);
                bb[4] = pack_bcast(b1.x);
                bb[5] = pack_bcast(b1.y);
                bb[6] = pack_bcast(b1.z);
                bb[7] = pack_bcast(b1.w);
#pragma unroll
                for (int ri = 0; ri < 4; ++ri)
#pragma unroll
                    for (int j = 0; j < 8; ++j)
                        acc[ri][j] = ffma2(a2[ri], bb[j], acc[ri][j]);
            }
        }

        // Epilogue: score = csq - 2*dot ; fold into running per-row min.
        float csq[8];
#pragma unroll
        for (int j = 0; j < 8; ++j) csq[j] = g_csq[n0 + colbase + j];

#pragma unroll
        for (int ri = 0; ri < 4; ++ri) {
            float bv0 = __int_as_float(0x7f800000);  // +inf
            float bv1 = __int_as_float(0x7f800000);
            int bj0 = 0, bj1 = 0;
#pragma unroll
            for (int j = 0; j < 8; ++j) {
                float2 d = unpack2(acc[ri][j]);
                float s0 = csq[j] - 2.f * d.x;  // row rowbase + 2*ri
                float s1 = csq[j] - 2.f * d.y;  // row rowbase + 2*ri + 1
                if (s0 < bv0) { bv0 = s0; bj0 = j; }
                if (s1 < bv1) { bv1 = s1; bj1 = j; }
            }
            unsigned long long key0 =
                ((unsigned long long)sortable_f32(bv0) << 32) |
                (unsigned)(n0 + colbase + bj0);
            unsigned long long key1 =
                ((unsigned long long)sortable_f32(bv1) << 32) |
                (unsigned)(n0 + colbase + bj1);
            atomicMin(&best[rowbase + 2 * ri], key0);
            atomicMin(&best[rowbase + 2 * ri + 1], key1);
        }
    }

    __syncthreads();
    if (tid < BM) g_labels[m0 + tid] = (int)(best[tid] & 0xFFFFFFFFull);
}

// ---- kernel 3: write labels + gather assigned centroids ---------------------
__global__ void gather_kernel(const float* __restrict__ cent,
                              float* __restrict__ out_labels,
                              float* __restrict__ out_assigned, int B) {
    int gtid = blockIdx.x * blockDim.x + threadIdx.x;
    if (out_labels && gtid < B) out_labels[gtid] = (float)g_labels[gtid];
    if (!out_assigned) return;
    const int total4 = B * (DIMS / 4);
    const float4* c4 = reinterpret_cast<const float4*>(cent);
    float4* o4 = reinterpret_cast<float4*>(out_assigned);
    for (int idx = gtid; idx < total4; idx += gridDim.x * blockDim.x) {
        int pt = idx >> 7;   // DIMS/4 == 128
        int d4 = idx & 127;
        int lab = g_labels[pt];
        o4[idx] = c4[(size_t)lab * 128 + d4];
    }
}

// ---------------------------------------------------------------------------
extern "C" void kernel_launch(void* const* d_in, const int* in_sizes, int n_in,
                              void* d_out, int out_size) {
    const float* x = (const float*)d_in[0];
    const float* cent = (const float*)d_in[1];
    const int B = in_sizes[0] / DIMS;  // 32768
    const int K = in_sizes[1] / DIMS;  // 2048

    float* out = (float*)d_out;
    float* out_labels = nullptr;
    float* out_assigned = nullptr;
    if (out_size == B * (DIMS + 1)) {          // labels then assigned (tuple order)
        out_labels = out;
        out_assigned = out + B;
    } else if (out_size == B * DIMS) {         // assigned only
        out_assigned = out;
    } else {                                   // labels only
        out_labels = out;
    }

    csq_kernel<<<(K + 255) / 256, 256>>>(cent, K);
    assign_kernel<<<B / BM, 256>>>(x, cent, K);

    int total4 = B * (DIMS / 4);
    int gblocks = (total4 + 255) / 256;
    gather_kernel<<<gblocks, 256>>>(cent, out_labels, out_assigned, B);
}

// round 3
// speedup vs baseline: 1.7818x; 1.7818x over previous
#include <cuda_runtime.h>
#include <cuda_bf16.h>
#include <cstdint>

// ---------------------------------------------------------------------------
// KMeans assignment via warp-level bf16 HMMA (mma.sync, base sm_103 features).
//   x: (32768,512) f32, centroids: (2048,512) f32
//   labels = argmin_k ( c_sq[k] - 2*(x+eps).c_k ); assigned = centroids[labels]
// bf16x3 limbs: dot ~= xh.ch + xh.cl + xl.ch (fp32 acc), err ~1e-4.
// Rows with (best2-best1) < MARGIN get an exact fp32 recompute.
// ---------------------------------------------------------------------------

#define EPSF   1e-6f
#define DIMS   512
#define MARGIN 0.02f
#define MAX_B  32768
#define MAX_K  2048

#define TM 128          // rows per CTA
#define TN 256          // centroids per n-tile
#define BKC 64          // bf16 k per chunk (128B rows)
#define NTHREADS 512    // 16 warps: 4 (m) x 4 (n); warp tile 32x64

__device__ __nv_bfloat16 g_xpk[(size_t)MAX_B * 1024];   // [row][ hi512 | lo512 ]
__device__ __nv_bfloat16 g_cpk[(size_t)MAX_K * 1024];
__device__ float g_csq[MAX_K];
__device__ int   g_labels[MAX_B];
__device__ float g_gap[MAX_B];

// ------------------------------ helpers -------------------------------------
__device__ __forceinline__ uint32_t smem_u32(const void* p) {
    uint32_t a;
    asm("{ .reg .u64 t; cvta.to.shared.u64 t, %1; cvt.u32.u64 %0, t; }"
        : "=r"(a) : "l"(p));
    return a;
}
#define SWZ128(o) ((o) ^ (((o) >> 3) & 0x70))

__device__ __forceinline__ void cp_async16(uint32_t s, const void* g) {
    asm volatile("cp.async.cg.shared.global [%0], [%1], 16;"
                 :: "r"(s), "l"(g) : "memory");
}
#define CP_COMMIT() asm volatile("cp.async.commit_group;" ::: "memory")
#define CP_WAIT1()  asm volatile("cp.async.wait_group 1;" ::: "memory")

__device__ __forceinline__ void ldsm_x4(uint32_t a, uint32_t& r0, uint32_t& r1,
                                        uint32_t& r2, uint32_t& r3) {
    asm volatile("ldmatrix.sync.aligned.m8n8.x4.shared.b16 {%0,%1,%2,%3}, [%4];"
                 : "=r"(r0), "=r"(r1), "=r"(r2), "=r"(r3) : "r"(a));
}
__device__ __forceinline__ void ldsm_x2(uint32_t a, uint32_t& r0, uint32_t& r1) {
    asm volatile("ldmatrix.sync.aligned.m8n8.x2.shared.b16 {%0,%1}, [%2];"
                 : "=r"(r0), "=r"(r1) : "r"(a));
}
__device__ __forceinline__ void mma16816(float* d, const uint32_t* a,
                                         const uint32_t* b) {
    asm volatile(
        "mma.sync.aligned.m16n8k16.row.col.f32.bf16.bf16.f32 "
        "{%0,%1,%2,%3}, {%4,%5,%6,%7}, {%8,%9}, {%0,%1,%2,%3};"
        : "+f"(d[0]), "+f"(d[1]), "+f"(d[2]), "+f"(d[3])
        : "r"(a[0]), "r"(a[1]), "r"(a[2]), "r"(a[3]), "r"(b[0]), "r"(b[1]));
}
__device__ __forceinline__ uint32_t pack_bf(__nv_bfloat16 a, __nv_bfloat16 b) {
    __nv_bfloat162 t; t.x = a; t.y = b;
    return *reinterpret_cast<uint32_t*>(&t);
}
__device__ __forceinline__ unsigned sortable_f32(float f) {
    unsigned u = __float_as_uint(f);
    return (u & 0x80000000u) ? ~u : (u | 0x80000000u);
}
__device__ __forceinline__ float unsortable_f32(unsigned u) {
    return (u & 0x80000000u) ? __uint_as_float(u ^ 0x80000000u)
                             : __uint_as_float(~u);
}

// ---- prep: split fp32 rows into bf16 hi/lo limbs: [hi 512 | lo 512] --------
__global__ void prep_kernel(const float* __restrict__ src, int is_x) {
    int g = blockIdx.x * 256 + threadIdx.x;
    int row = g >> 4, ch = g & 15;
    float eps = is_x ? EPSF : 0.f;
    const float4* s4 =
        reinterpret_cast<const float4*>(src + (size_t)row * DIMS + ch * 32);
    uint32_t hi[16], lo[16];
#pragma unroll
    for (int q = 0; q < 8; ++q) {
        float4 f = s4[q];
        float e0 = f.x + eps, e1 = f.y + eps, e2 = f.z + eps, e3 = f.w + eps;
        __nv_bfloat16 h0 = __float2bfloat16(e0), h1 = __float2bfloat16(e1);
        __nv_bfloat16 h2 = __float2bfloat16(e2), h3 = __float2bfloat16(e3);
        __nv_bfloat16 l0 = __float2bfloat16(e0 - __bfloat162float(h0));
        __nv_bfloat16 l1 = __float2bfloat16(e1 - __bfloat162float(h1));
        __nv_bfloat16 l2 = __float2bfloat16(e2 - __bfloat162float(h2));
        __nv_bfloat16 l3 = __float2bfloat16(e3 - __bfloat162float(h3));
        hi[q * 2] = pack_bf(h0, h1); hi[q * 2 + 1] = pack_bf(h2, h3);
        lo[q * 2] = pack_bf(l0, l1); lo[q * 2 + 1] = pack_bf(l2, l3);
    }
    __nv_bfloat16* base = is_x ? g_xpk : g_cpk;
    uint4* dh = reinterpret_cast<uint4*>(base + (size_t)row * 1024 + ch * 32);
    uint4* dl = reinterpret_cast<uint4*>(base + (size_t)row * 1024 + 512 + ch * 32);
#pragma unroll
    for (int q = 0; q < 4; ++q)
        dh[q] = make_uint4(hi[4 * q], hi[4 * q + 1], hi[4 * q + 2], hi[4 * q + 3]);
#pragma unroll
    for (int q = 0; q < 4; ++q)
        dl[q] = make_uint4(lo[4 * q], lo[4 * q + 1], lo[4 * q + 2], lo[4 * q + 3]);
}

// ---- centroid squared norms (warp per row) ----------------------------------
__global__ void csq_kernel(const float* __restrict__ cent, int K) {
    int gt = blockIdx.x * 256 + threadIdx.x;
    int w = gt >> 5, lane = gt & 31;
    if (w >= K) return;
    const float4* row = reinterpret_cast<const float4*>(cent + (size_t)w * DIMS);
    float s = 0.f;
#pragma unroll
    for (int i = 0; i < 4; ++i) {
        float4 v = row[lane + 32 * i];
        s += v.x * v.x + v.y * v.y + v.z * v.z + v.w * v.w;
    }
#pragma unroll
    for (int o = 16; o; o >>= 1) s += __shfl_xor_sync(0xffffffffu, s, o);
    if (!lane) g_csq[w] = s;
}

// ---- main HMMA kernel --------------------------------------------------------
// smem: best1[128] u64, best2[128] u32, then 3 stages of (A 16KB + B 32KB).
#define STAGE_BYTES (TM * 128 + TN * 128)  // 49152
#define SM_STAGE0   2048
#define SM_BYTES    (SM_STAGE0 + 3 * STAGE_BYTES)

__global__ __launch_bounds__(NTHREADS, 1)
void assign_mma_kernel(int K) {
    extern __shared__ char smem[];
    unsigned long long* best1 = reinterpret_cast<unsigned long long*>(smem);
    unsigned* best2 = reinterpret_cast<unsigned*>(smem + TM * 8);
    const uint32_t sb = smem_u32(smem);

    const int tid = threadIdx.x;
    const int lane = tid & 31;
    const int wid = tid >> 5;
    const int warp_m = wid & 3;   // 4 warps along M (32 rows each)
    const int warp_n = wid >> 2;  // 4 warps along N (64 cols each)
    const int m0 = blockIdx.x * TM;

    if (tid < TM) { best1[tid] = ~0ull; best2[tid] = 0xFFFFFFFFu; }

    const int NT = K / TN;          // 8 n-tiles
    const int T = NT * 24;          // 24 k-iters per n-tile (3 products x 8)

    // ---- cp.async stage loader ----
    auto load_stage = [&](int j) {
        const int nt = j / 24, kc = j % 24;
        const int p = kc >> 3, c = kc & 7;
        const int ka = (p < 2 ? 0 : 512) + c * 64;
        const int kb = (p == 1 ? 512 : 0) + c * 64;
        const int n0 = nt * TN;
        const uint32_t abase = sb + SM_STAGE0 + (j % 3) * STAGE_BYTES;
        const uint32_t bbase = abase + TM * 128;
#pragma unroll
        for (int i = 0; i < 2; ++i) {  // A: 1024 16B chunks / 512 thr
            int idx = i * NTHREADS + tid;
            int r = idx >> 3, q = idx & 7;
            cp_async16(abase + SWZ128(r * 128 + q * 16),
                       g_xpk + (size_t)(m0 + r) * 1024 + ka + q * 8);
        }
#pragma unroll
        for (int i = 0; i < 4; ++i) {  // B: 2048 chunks / 512 thr
            int idx = i * NTHREADS + tid;
            int r = idx >> 3, q = idx & 7;
            cp_async16(bbase + SWZ128(r * 128 + q * 16),
                       g_cpk + (size_t)(n0 + r) * 1024 + kb + q * 8);
        }
    };

    float acc[2][8][4];
#pragma unroll
    for (int fm = 0; fm < 2; ++fm)
#pragma unroll
        for (int fn = 0; fn < 8; ++fn)
#pragma unroll
            for (int q = 0; q < 4; ++q) acc[fm][fn][q] = 0.f;

    // running per-row-slot best1/best2/idx (4 slots: 2 m-frags x 2 row halves)
    float rb1[4], rb2[4];
    int ri[4];
#pragma unroll
    for (int s = 0; s < 4; ++s) {
        rb1[s] = __int_as_float(0x7f800000);
        rb2[s] = rb1[s];
        ri[s] = 0;
    }

    load_stage(0); CP_COMMIT();
    load_stage(1); CP_COMMIT();

    for (int j = 0; j < T; ++j) {
        CP_WAIT1();
        __syncthreads();
        const uint32_t abase = sb + SM_STAGE0 + (j % 3) * STAGE_BYTES;
        const uint32_t bbase = abase + TM * 128;

#pragma unroll
        for (int ks = 0; ks < 4; ++ks) {
            uint32_t a[2][4], b[8][2];
#pragma unroll
            for (int fm = 0; fm < 2; ++fm) {
                int r = warp_m * 32 + fm * 16 + (lane & 15);
                uint32_t addr = abase +
                    SWZ128((uint32_t)(r * 128 + ks * 32 + ((lane >> 4) & 1) * 16));
                ldsm_x4(addr, a[fm][0], a[fm][1], a[fm][2], a[fm][3]);
            }
#pragma unroll
            for (int fn = 0; fn < 8; ++fn) {
                int r = warp_n * 64 + fn * 8 + (lane & 7);
                uint32_t addr = bbase +
                    SWZ128((uint32_t)(r * 128 + ks * 32 + ((lane >> 3) & 1) * 16));
                ldsm_x2(addr, b[fn][0], b[fn][1]);
            }
#pragma unroll
            for (int fm = 0; fm < 2; ++fm)
#pragma unroll
                for (int fn = 0; fn < 8; ++fn)
                    mma16816(acc[fm][fn], a[fm], b[fn]);
        }

        if (j + 2 < T) load_stage(j + 2);
        CP_COMMIT();

        if ((j % 24) == 23) {
            // ---- epilogue for this n-tile: fold scores into running best ----
            const int n0 = (j / 24) * TN;
#pragma unroll
            for (int fn = 0; fn < 8; ++fn) {
                int c0 = n0 + warp_n * 64 + fn * 8 + (lane & 3) * 2;
                float q0 = g_csq[c0], q1 = g_csq[c0 + 1];
#pragma unroll
                for (int fm = 0; fm < 2; ++fm) {
                    float s00 = fmaf(-2.f, acc[fm][fn][0], q0);
                    float s01 = fmaf(-2.f, acc[fm][fn][1], q1);
                    float s10 = fmaf(-2.f, acc[fm][fn][2], q0);
                    float s11 = fmaf(-2.f, acc[fm][fn][3], q1);
                    int s0 = fm * 2, s1 = fm * 2 + 1;
                    if (s00 < rb1[s0]) { rb2[s0] = rb1[s0]; rb1[s0] = s00; ri[s0] = c0; }
                    else if (s00 < rb2[s0]) rb2[s0] = s00;
                    if (s01 < rb1[s0]) { rb2[s0] = rb1[s0]; rb1[s0] = s01; ri[s0] = c0 + 1; }
                    else if (s01 < rb2[s0]) rb2[s0] = s01;
                    if (s10 < rb1[s1]) { rb2[s1] = rb1[s1]; rb1[s1] = s10; ri[s1] = c0; }
                    else if (s10 < rb2[s1]) rb2[s1] = s10;
                    if (s11 < rb1[s1]) { rb2[s1] = rb1[s1]; rb1[s1] = s11; ri[s1] = c0 + 1; }
                    else if (s11 < rb2[s1]) rb2[s1] = s11;
                    acc[fm][fn][0] = 0.f; acc[fm][fn][1] = 0.f;
                    acc[fm][fn][2] = 0.f; acc[fm][fn][3] = 0.f;
                }
            }
        }
    }

    // ---- final reduction: lanes sharing a row (same lane>>2) merge ----------
#pragma unroll
    for (int s = 0; s < 4; ++s) {
#pragma unroll
        for (int d = 1; d <= 2; d <<= 1) {
            float ob1 = __shfl_xor_sync(0xffffffffu, rb1[s], d);
            float ob2 = __shfl_xor_sync(0xffffffffu, rb2[s], d);
            int oi = __shfl_xor_sync(0xffffffffu, ri[s], d);
            if (ob1 < rb1[s] || (ob1 == rb1[s] && oi < ri[s])) {
                rb2[s] = fminf(rb1[s], ob2);
                rb1[s] = ob1; ri[s] = oi;
            } else {
                rb2[s] = fminf(rb2[s], ob1);
            }
        }
    }
    if ((lane & 3) == 0) {
#pragma unroll
        for (int s = 0; s < 4; ++s) {
            int row = warp_m * 32 + (s >> 1) * 16 + (lane >> 2) + (s & 1) * 8;
            unsigned long long key =
                ((unsigned long long)sortable_f32(rb1[s]) << 32) | (unsigned)ri[s];
            atomicMin(&best1[row], key);
        }
    }
    __syncthreads();
    if ((lane & 3) == 0) {
#pragma unroll
        for (int s = 0; s < 4; ++s) {
            int row = warp_m * 32 + (s >> 1) * 16 + (lane >> 2) + (s & 1) * 8;
            unsigned long long k1 = best1[row];
            float contrib = ((int)(k1 & 0xFFFFFFFFull) == ri[s]) ? rb2[s] : rb1[s];
            atomicMin(&best2[row], sortable_f32(contrib));
        }
    }
    __syncthreads();
    if (tid < TM) {
        unsigned long long k1 = best1[tid];
        g_labels[m0 + tid] = (int)(k1 & 0xFFFFFFFFull);
        g_gap[m0 + tid] =
            unsortable_f32(best2[tid]) - unsortable_f32((unsigned)(k1 >> 32));
    }
}

// ---- exact fp32 recompute for ambiguous rows ---------------------------------
__global__ void cleanup_kernel(const float* __restrict__ x,
                               const float* __restrict__ cent, int K) {
    const int row = blockIdx.x;
    if (g_gap[row] >= MARGIN) return;
    __shared__ float xr[DIMS];
    __shared__ unsigned long long best;
    const int tid = threadIdx.x;
    if (tid == 0) best = ~0ull;
    for (int i = tid; i < DIMS; i += 256) xr[i] = x[(size_t)row * DIMS + i] + EPSF;
    __syncthreads();
    const float4* xr4 = reinterpret_cast<const float4*>(xr);
    for (int c = tid; c < K; c += 256) {
        const float4* cr = reinterpret_cast<const float4*>(cent + (size_t)c * DIMS);
        float s = 0.f;
#pragma unroll 8
        for (int i = 0; i < DIMS / 4; ++i) {
            float4 v = cr[i], u = xr4[i];
            s += u.x * v.x + u.y * v.y + u.z * v.z + u.w * v.w;
        }
        float score = g_csq[c] - 2.f * s;
        unsigned long long key =
            ((unsigned long long)sortable_f32(score) << 32) | (unsigned)c;
        atomicMin(&best, key);
    }
    __syncthreads();
    if (tid == 0) g_labels[row] = (int)(best & 0xFFFFFFFFull);
}

// ---- outputs -----------------------------------------------------------------
__global__ void gather_kernel(const float* __restrict__ cent,
                              float* __restrict__ out_labels,
                              float* __restrict__ out_assigned, int B) {
    int gtid = blockIdx.x * blockDim.x + threadIdx.x;
    if (out_labels && gtid < B) out_labels[gtid] = (float)g_labels[gtid];
    if (!out_assigned) return;
    const int total4 = B * (DIMS / 4);
    const float4* c4 = reinterpret_cast<const float4*>(cent);
    float4* o4 = reinterpret_cast<float4*>(out_assigned);
    for (int idx = gtid; idx < total4; idx += gridDim.x * blockDim.x) {
        int pt = idx >> 7;
        int d4 = idx & 127;
        int lab = g_labels[pt];
        o4[idx] = c4[(size_t)lab * 128 + d4];
    }
}

// ---------------------------------------------------------------------------
extern "C" void kernel_launch(void* const* d_in, const int* in_sizes, int n_in,
                              void* d_out, int out_size) {
    const float* x = (const float*)d_in[0];
    const float* cent = (const float*)d_in[1];
    const int B = in_sizes[0] / DIMS;  // 32768
    const int K = in_sizes[1] / DIMS;  // 2048

    float* out = (float*)d_out;
    float* out_labels = nullptr;
    float* out_assigned = nullptr;
    if (out_size == B * (DIMS + 1)) { out_labels = out; out_assigned = out + B; }
    else if (out_size == B * DIMS)  { out_assigned = out; }
    else                            { out_labels = out; }

    cudaFuncSetAttribute(assign_mma_kernel,
                         cudaFuncAttributeMaxDynamicSharedMemorySize, SM_BYTES);

    prep_kernel<<<(B * 16) / 256, 256>>>(x, 1);
    prep_kernel<<<(K * 16) / 256, 256>>>(cent, 0);
    csq_kernel<<<(K * 32) / 256, 256>>>(cent, K);
    assign_mma_kernel<<<B / TM, NTHREADS, SM_BYTES>>>(K);
    cleanup_kernel<<<B, 256>>>(x, cent, K);

    int total4 = B * (DIMS / 4);
    gather_kernel<<<(total4 + 255) / 256, 256>>>(cent, out_labels, out_assigned, B);
}